// round 4
// baseline (speedup 1.0000x reference)
#include <cuda_runtime.h>
#include <cstdint>

typedef unsigned long long ull;

// Problem constants
#define B_  2048
#define T_  512
#define I_  58
#define KP_ 60          // padded k (multiple of 4)
#define H_  23
#define G_  69          // 3*H
#define GP_ 72          // padded gate dim
#define ROWS_ (B_*T_)   // 1048576

// Scratch for x_proj: [B*T][72] padded
__device__ float g_xproj[(size_t)ROWS_ * GP_];

// ---------------- f32x2 helpers ----------------
__device__ __forceinline__ ull pk2(float a, float b) {
    ull r;
    asm("mov.b64 %0, {%1, %2};" : "=l"(r) : "f"(a), "f"(b));
    return r;
}
__device__ __forceinline__ void upk2(ull v, float& a, float& b) {
    asm("mov.b64 {%0, %1}, %2;" : "=f"(a), "=f"(b) : "l"(v));
}
__device__ __forceinline__ ull ffma2(ull a, ull b, ull c) {
    ull d;
    asm("fma.rn.f32x2 %0, %1, %2, %3;" : "=l"(d) : "l"(a), "l"(b), "l"(c));
    return d;
}
// ---------------- fast transcendentals ----------------
__device__ __forceinline__ float fex2(float x) {
    float y; asm("ex2.approx.f32 %0, %1;" : "=f"(y) : "f"(x)); return y;
}
__device__ __forceinline__ float frcp(float x) {
    float y; asm("rcp.approx.f32 %0, %1;" : "=f"(y) : "f"(x)); return y;
}
__device__ __forceinline__ float fsigmoid(float x) {
    return frcp(1.0f + fex2(-1.4426950408889634f * x));
}
__device__ __forceinline__ float ftanh(float x) {
    float e = fex2(2.8853900817779268f * x);
    return fmaf(-2.0f, frcp(e + 1.0f), 1.0f);
}

// ============================================================================
// Kernel 1: x_proj = task @ W_ih^T + b_ih
//   192 threads, 128 rows/block. Thread: 4 rows x 6 g-pairs (48 outputs).
//   k padded to 60: x consumed as LDS.128 quads over k, w pairs as LDS.128.
// ============================================================================
__global__ __launch_bounds__(192, 4) void gemm_xproj_kernel(
    const float* __restrict__ task,   // [B*T][58]
    const float* __restrict__ Wih,    // [69][58]
    const float* __restrict__ bih)    // [69]
{
    // xs: [128][60] floats (30720B) ; ws: [60][36] ull g-pairs (17280B)
    // total 48000B; later reused as os[128][36] ull (36864B)
    __shared__ __align__(16) char sraw[128 * KP_ * 4 + KP_ * 36 * 8];
    float* xs = reinterpret_cast<float*>(sraw);
    ull*   ws = reinterpret_cast<ull*>(sraw + 128 * KP_ * 4);
    __shared__ __align__(16) ull bs[36];

    const int tid = threadIdx.x;
    const size_t rowbase = (size_t)blockIdx.x * 128;

    // Stage x tile: coalesced float4 loads, scatter to 60-padded rows
    {
        const float4* src = reinterpret_cast<const float4*>(task + rowbase * I_);
        // 1856 vectors = 9*192 + 128
        #pragma unroll
        for (int it = 0; it < 10; it++) {
            int v = tid + it * 192;
            if (it < 9 || tid < 128) {
                float4 f = src[v];
                int e = 4 * v;
                int r = e / I_, c = e - r * I_;
                // scatter 4 elements (may cross row boundary)
                float vals[4] = {f.x, f.y, f.z, f.w};
                #pragma unroll
                for (int q = 0; q < 4; q++) {
                    int rr = r, cc = c + q;
                    if (cc >= I_) { rr += 1; cc -= I_; }
                    xs[rr * KP_ + cc] = vals[q];
                }
            }
        }
        // zero pad cols 58,59
        for (int i = tid; i < 256; i += 192) {
            int r = i >> 1, c = I_ + (i & 1);
            xs[r * KP_ + c] = 0.0f;
        }
    }
    // Stage weights as (k, g-pair); zero beyond k=57 / g=68
    for (int i = tid; i < KP_ * 36; i += 192) {
        int k = i / 36, p = i - 36 * k;
        int g0 = 2 * p;
        float w0 = (k < I_ && g0     < G_) ? Wih[g0 * I_ + k]       : 0.0f;
        float w1 = (k < I_ && g0 + 1 < G_) ? Wih[(g0 + 1) * I_ + k] : 0.0f;
        float2 wp = make_float2(w0, w1);
        ws[i] = *reinterpret_cast<ull*>(&wp);
    }
    if (tid < 36) {
        int g0 = 2 * tid;
        float b0 = (g0     < G_) ? bih[g0]     : 0.0f;
        float b1 = (g0 + 1 < G_) ? bih[g0 + 1] : 0.0f;
        float2 bp = make_float2(b0, b1);
        bs[tid] = *reinterpret_cast<ull*>(&bp);
    }
    __syncthreads();

    const int gg = tid % 6;      // 6 pair-tiles of 6 pairs = 36 pairs = 72 g
    const int rg = tid / 6;      // 32 row groups of 4 rows
    const int r0 = rg * 4;
    const ull* wbase = ws + gg * 6;
    const float* xbase = xs + r0 * KP_;

    ull acc[4][6];
    #pragma unroll
    for (int p = 0; p < 6; p++) {
        ull bb = bs[gg * 6 + p];
        acc[0][p] = bb; acc[1][p] = bb; acc[2][p] = bb; acc[3][p] = bb;
    }

    #pragma unroll
    for (int kc = 0; kc < KP_ / 4; kc++) {
        // 4 rows x 4 k's via LDS.128 (rows 60-padded -> 16B aligned)
        float4 xq[4];
        #pragma unroll
        for (int i = 0; i < 4; i++)
            xq[i] = *reinterpret_cast<const float4*>(xbase + i * KP_ + kc * 4);

        #pragma unroll
        for (int kk = 0; kk < 4; kk++) {
            ull X[4];
            #pragma unroll
            for (int i = 0; i < 4; i++) {
                float xv = (kk == 0) ? xq[i].x : (kk == 1) ? xq[i].y
                         : (kk == 2) ? xq[i].z : xq[i].w;
                X[i] = pk2(xv, xv);
            }
            const ulonglong2* wk =
                reinterpret_cast<const ulonglong2*>(wbase + (kc * 4 + kk) * 36);
            ulonglong2 wA = wk[0], wB = wk[1], wC = wk[2];
            #pragma unroll
            for (int i = 0; i < 4; i++) {
                acc[i][0] = ffma2(X[i], wA.x, acc[i][0]);
                acc[i][1] = ffma2(X[i], wA.y, acc[i][1]);
                acc[i][2] = ffma2(X[i], wB.x, acc[i][2]);
                acc[i][3] = ffma2(X[i], wB.y, acc[i][3]);
                acc[i][4] = ffma2(X[i], wC.x, acc[i][4]);
                acc[i][5] = ffma2(X[i], wC.y, acc[i][5]);
            }
        }
    }

    __syncthreads();   // xs/ws dead; reuse as output stage
    ull* os = reinterpret_cast<ull*>(sraw);   // [128][36] pairs
    #pragma unroll
    for (int i = 0; i < 4; i++) {
        #pragma unroll
        for (int p = 0; p < 6; p++) {
            os[(r0 + i) * 36 + gg * 6 + p] = acc[i][p];
        }
    }
    __syncthreads();
    // Coalesced float4 streamout: 2304 vectors, 12 per thread
    {
        const float4* src = reinterpret_cast<const float4*>(sraw);
        float4* dst = reinterpret_cast<float4*>(g_xproj + rowbase * GP_);
        #pragma unroll
        for (int it = 0; it < 12; it++) {
            int idx = tid + it * 192;
            dst[idx] = src[idx];
        }
    }
}

// ============================================================================
// Kernel 2: GRU scan. ONE warp per block, TWO batch rows per warp.
//   Lane j = hidden unit for both rows; weights shared across rows (regs).
//   Two independent dependency chains per warp -> fills issue slots.
//   h double-buffered in smem; bias in pad slot h[23]==1; 2-step x prefetch.
// ============================================================================
__global__ __launch_bounds__(32) void gru_scan_kernel(
    const float* __restrict__ Whh,    // [69][23]
    const float* __restrict__ bhh,    // [69]
    const float* __restrict__ piw,    // [23]
    const float* __restrict__ pib,    // [23]
    float* __restrict__ out_action,   // [B][T][23]
    float* __restrict__ out_hidden)   // [B][23]
{
    __shared__ __align__(16) float hsm[2][2][32];   // [row][buf][unit]

    const int j  = threadIdx.x;
    const int bA = blockIdx.x * 2;
    const int bB = bA + 1;
    const int jc = (j < H_) ? j : (H_ - 1);
    const bool act = (j < H_);

    // W_hh rows for unit jc, 12 k-pairs; pad slot carries b_hh (h[23]==1)
    ull WR[12], WZ[12], WN[12];
    {
        const float* wr = Whh + (size_t)jc * H_;
        const float* wz = Whh + (size_t)(H_ + jc) * H_;
        const float* wn = Whh + (size_t)(2 * H_ + jc) * H_;
        #pragma unroll
        for (int m = 0; m < 11; m++) {
            WR[m] = pk2(wr[2 * m], wr[2 * m + 1]);
            WZ[m] = pk2(wz[2 * m], wz[2 * m + 1]);
            WN[m] = pk2(wn[2 * m], wn[2 * m + 1]);
        }
        WR[11] = pk2(wr[22], bhh[jc]);
        WZ[11] = pk2(wz[22], bhh[H_ + jc]);
        WN[11] = pk2(wn[22], bhh[2 * H_ + jc]);
    }
    const float pw = piw[jc], pb = pib[jc];

    // init both buffers, both rows: zeros + pad slot = 1.0
    {
        float v = (j == 23) ? 1.0f : 0.0f;
        hsm[0][0][j] = v; hsm[0][1][j] = v;
        hsm[1][0][j] = v; hsm[1][1][j] = v;
    }
    __syncwarp();

    const float* xpA = g_xproj + (size_t)bA * T_ * GP_;
    const float* xpB = g_xproj + (size_t)bB * T_ * GP_;
    float* outA = out_action + (size_t)bA * T_ * H_;
    float* outB = out_action + (size_t)bB * T_ * H_;
    const int o0 = jc, o1 = H_ + jc, o2 = 2 * H_ + jc;

    // pipeline: cur set (even steps) + alt set (odd steps), 2-step lead
    float cA[3], cB[3], pA[3], pB[3];
    cA[0] = xpA[o0];        cA[1] = xpA[o1];        cA[2] = xpA[o2];
    cB[0] = xpB[o0];        cB[1] = xpB[o1];        cB[2] = xpB[o2];
    pA[0] = xpA[GP_ + o0];  pA[1] = xpA[GP_ + o1];  pA[2] = xpA[GP_ + o2];
    pB[0] = xpB[GP_ + o0];  pB[1] = xpB[GP_ + o1];  pB[2] = xpB[GP_ + o2];

    float hA = 0.0f, hB = 0.0f;

    #pragma unroll 1
    for (int t = 0; t < T_; t += 2) {
        // ================= step t (read buf0 -> write buf1, use c*) =========
        {
            // prefetch t+2 into c* (consumed 2 steps later)
            int tn = (t + 2 < T_) ? t + 2 : T_ - 1;
            const float* nA_ = xpA + (size_t)tn * GP_;
            const float* nB_ = xpB + (size_t)tn * GP_;
            float fA0 = nA_[o0], fA1 = nA_[o1], fA2 = nA_[o2];
            float fB0 = nB_[o0], fB1 = nB_[o1], fB2 = nB_[o2];

            const ulonglong2* hqA = reinterpret_cast<const ulonglong2*>(hsm[0][0]);
            const ulonglong2* hqB = reinterpret_cast<const ulonglong2*>(hsm[1][0]);
            ull aRA = 0, aZA = 0, aNA = 0, aRB = 0, aZB = 0, aNB = 0;
            #pragma unroll
            for (int m = 0; m < 6; m++) {
                ulonglong2 qA = hqA[m];
                ulonglong2 qB = hqB[m];
                aRA = ffma2(WR[2*m], qA.x, aRA); aRA = ffma2(WR[2*m+1], qA.y, aRA);
                aRB = ffma2(WR[2*m], qB.x, aRB); aRB = ffma2(WR[2*m+1], qB.y, aRB);
                aZA = ffma2(WZ[2*m], qA.x, aZA); aZA = ffma2(WZ[2*m+1], qA.y, aZA);
                aZB = ffma2(WZ[2*m], qB.x, aZB); aZB = ffma2(WZ[2*m+1], qB.y, aZB);
                aNA = ffma2(WN[2*m], qA.x, aNA); aNA = ffma2(WN[2*m+1], qA.y, aNA);
                aNB = ffma2(WN[2*m], qB.x, aNB); aNB = ffma2(WN[2*m+1], qB.y, aNB);
            }
            float x0, x1;
            upk2(aRA, x0, x1); float rA = fsigmoid(cA[0] + x0 + x1);
            upk2(aZA, x0, x1); float zA = fsigmoid(cA[1] + x0 + x1);
            upk2(aNA, x0, x1); float nA = ftanh(fmaf(rA, x0 + x1, cA[2]));
            upk2(aRB, x0, x1); float rB = fsigmoid(cB[0] + x0 + x1);
            upk2(aZB, x0, x1); float zB = fsigmoid(cB[1] + x0 + x1);
            upk2(aNB, x0, x1); float nB = ftanh(fmaf(rB, x0 + x1, cB[2]));
            float hnA = fmaf(zA, hA - nA, nA);
            float hnB = fmaf(zB, hB - nB, nB);

            if (act) { hsm[0][1][j] = hnA; hsm[1][1][j] = hnB; }
            __syncwarp();
            if (act) {
                outA[(size_t)t * H_ + j] = fmaf(pw, hnA, pb);
                outB[(size_t)t * H_ + j] = fmaf(pw, hnB, pb);
            }
            hA = hnA; hB = hnB;
            cA[0] = fA0; cA[1] = fA1; cA[2] = fA2;
            cB[0] = fB0; cB[1] = fB1; cB[2] = fB2;
        }
        // ================= step t+1 (read buf1 -> write buf0, use p*) =======
        {
            int tn = (t + 3 < T_) ? t + 3 : T_ - 1;
            const float* nA_ = xpA + (size_t)tn * GP_;
            const float* nB_ = xpB + (size_t)tn * GP_;
            float fA0 = nA_[o0], fA1 = nA_[o1], fA2 = nA_[o2];
            float fB0 = nB_[o0], fB1 = nB_[o1], fB2 = nB_[o2];

            const ulonglong2* hqA = reinterpret_cast<const ulonglong2*>(hsm[0][1]);
            const ulonglong2* hqB = reinterpret_cast<const ulonglong2*>(hsm[1][1]);
            ull aRA = 0, aZA = 0, aNA = 0, aRB = 0, aZB = 0, aNB = 0;
            #pragma unroll
            for (int m = 0; m < 6; m++) {
                ulonglong2 qA = hqA[m];
                ulonglong2 qB = hqB[m];
                aRA = ffma2(WR[2*m], qA.x, aRA); aRA = ffma2(WR[2*m+1], qA.y, aRA);
                aRB = ffma2(WR[2*m], qB.x, aRB); aRB = ffma2(WR[2*m+1], qB.y, aRB);
                aZA = ffma2(WZ[2*m], qA.x, aZA); aZA = ffma2(WZ[2*m+1], qA.y, aZA);
                aZB = ffma2(WZ[2*m], qB.x, aZB); aZB = ffma2(WZ[2*m+1], qB.y, aZB);
                aNA = ffma2(WN[2*m], qA.x, aNA); aNA = ffma2(WN[2*m+1], qA.y, aNA);
                aNB = ffma2(WN[2*m], qB.x, aNB); aNB = ffma2(WN[2*m+1], qB.y, aNB);
            }
            float x0, x1;
            upk2(aRA, x0, x1); float rA = fsigmoid(pA[0] + x0 + x1);
            upk2(aZA, x0, x1); float zA = fsigmoid(pA[1] + x0 + x1);
            upk2(aNA, x0, x1); float nA = ftanh(fmaf(rA, x0 + x1, pA[2]));
            upk2(aRB, x0, x1); float rB = fsigmoid(pB[0] + x0 + x1);
            upk2(aZB, x0, x1); float zB = fsigmoid(pB[1] + x0 + x1);
            upk2(aNB, x0, x1); float nB = ftanh(fmaf(rB, x0 + x1, pB[2]));
            float hnA = fmaf(zA, hA - nA, nA);
            float hnB = fmaf(zB, hB - nB, nB);

            if (act) { hsm[0][0][j] = hnA; hsm[1][0][j] = hnB; }
            __syncwarp();
            if (act) {
                outA[(size_t)(t + 1) * H_ + j] = fmaf(pw, hnA, pb);
                outB[(size_t)(t + 1) * H_ + j] = fmaf(pw, hnB, pb);
            }
            hA = hnA; hB = hnB;
            pA[0] = fA0; pA[1] = fA1; pA[2] = fA2;
            pB[0] = fB0; pB[1] = fB1; pB[2] = fB2;
        }
    }

    if (act) {
        out_hidden[(size_t)bA * H_ + j] = hA;
        out_hidden[(size_t)bB * H_ + j] = hB;
    }
}

// ============================================================================
extern "C" void kernel_launch(void* const* d_in, const int* in_sizes, int n_in,
                              void* d_out, int out_size) {
    const float* task = (const float*)d_in[0];  // (2048,512,58)
    const float* Wih  = (const float*)d_in[1];  // (69,58)
    const float* Whh  = (const float*)d_in[2];  // (69,23)
    const float* bih  = (const float*)d_in[3];  // (69)
    const float* bhh  = (const float*)d_in[4];  // (69)
    const float* piw  = (const float*)d_in[5];  // (23)
    const float* pib  = (const float*)d_in[6];  // (23)

    float* out = (float*)d_out;
    float* action = out;                                  // B*T*H
    float* hidden = out + (size_t)B_ * T_ * H_;           // B*H

    gemm_xproj_kernel<<<ROWS_ / 128, 192>>>(task, Wih, bih);
    gru_scan_kernel<<<B_ / 2, 32>>>(Whh, bhh, piw, pib, action, hidden);
}

// round 5
// speedup vs baseline: 1.1737x; 1.1737x over previous
#include <cuda_runtime.h>
#include <cstdint>

typedef unsigned long long ull;

// Problem constants
#define B_  2048
#define T_  512
#define I_  58
#define KP_ 60          // padded k (multiple of 4)
#define H_  23
#define G_  69          // 3*H
#define GP_ 72          // padded gate dim
#define ROWS_ (B_*T_)   // 1048576

// Scratch for x_proj: [B*T][72] padded
__device__ float g_xproj[(size_t)ROWS_ * GP_];

// ---------------- f32x2 helpers ----------------
__device__ __forceinline__ ull pk2(float a, float b) {
    ull r;
    asm("mov.b64 %0, {%1, %2};" : "=l"(r) : "f"(a), "f"(b));
    return r;
}
__device__ __forceinline__ void upk2(ull v, float& a, float& b) {
    asm("mov.b64 {%0, %1}, %2;" : "=f"(a), "=f"(b) : "l"(v));
}
__device__ __forceinline__ ull ffma2(ull a, ull b, ull c) {
    ull d;
    asm("fma.rn.f32x2 %0, %1, %2, %3;" : "=l"(d) : "l"(a), "l"(b), "l"(c));
    return d;
}
// ---------------- fast transcendentals ----------------
__device__ __forceinline__ float fex2(float x) {
    float y; asm("ex2.approx.f32 %0, %1;" : "=f"(y) : "f"(x)); return y;
}
__device__ __forceinline__ float frcp(float x) {
    float y; asm("rcp.approx.f32 %0, %1;" : "=f"(y) : "f"(x)); return y;
}
__device__ __forceinline__ float fsigmoid(float x) {
    return frcp(1.0f + fex2(-1.4426950408889634f * x));
}
__device__ __forceinline__ float ftanh(float x) {
    float e = fex2(2.8853900817779268f * x);
    return fmaf(-2.0f, frcp(e + 1.0f), 1.0f);
}

// ============================================================================
// Kernel 1: x_proj = task @ W_ih^T + b_ih   (unchanged from Round 3 — passing)
// ============================================================================
__global__ __launch_bounds__(192, 4) void gemm_xproj_kernel(
    const float* __restrict__ task,   // [B*T][58]
    const float* __restrict__ Wih,    // [69][58]
    const float* __restrict__ bih)    // [69]
{
    __shared__ __align__(16) char sraw[128 * KP_ * 4 + KP_ * 36 * 8];
    float* xs = reinterpret_cast<float*>(sraw);
    ull*   ws = reinterpret_cast<ull*>(sraw + 128 * KP_ * 4);
    __shared__ __align__(16) ull bs[36];

    const int tid = threadIdx.x;
    const size_t rowbase = (size_t)blockIdx.x * 128;

    // Stage x tile: coalesced float4 loads, scatter to 60-padded rows
    {
        const float4* src = reinterpret_cast<const float4*>(task + rowbase * I_);
        #pragma unroll
        for (int it = 0; it < 10; it++) {
            int v = tid + it * 192;
            if (it < 9 || tid < 128) {
                float4 f = src[v];
                int e = 4 * v;
                int r = e / I_, c = e - r * I_;
                float vals[4] = {f.x, f.y, f.z, f.w};
                #pragma unroll
                for (int q = 0; q < 4; q++) {
                    int rr = r, cc = c + q;
                    if (cc >= I_) { rr += 1; cc -= I_; }
                    xs[rr * KP_ + cc] = vals[q];
                }
            }
        }
        for (int i = tid; i < 256; i += 192) {
            int r = i >> 1, c = I_ + (i & 1);
            xs[r * KP_ + c] = 0.0f;
        }
    }
    for (int i = tid; i < KP_ * 36; i += 192) {
        int k = i / 36, p = i - 36 * k;
        int g0 = 2 * p;
        float w0 = (k < I_ && g0     < G_) ? Wih[g0 * I_ + k]       : 0.0f;
        float w1 = (k < I_ && g0 + 1 < G_) ? Wih[(g0 + 1) * I_ + k] : 0.0f;
        float2 wp = make_float2(w0, w1);
        ws[i] = *reinterpret_cast<ull*>(&wp);
    }
    if (tid < 36) {
        int g0 = 2 * tid;
        float b0 = (g0     < G_) ? bih[g0]     : 0.0f;
        float b1 = (g0 + 1 < G_) ? bih[g0 + 1] : 0.0f;
        float2 bp = make_float2(b0, b1);
        bs[tid] = *reinterpret_cast<ull*>(&bp);
    }
    __syncthreads();

    const int gg = tid % 6;
    const int rg = tid / 6;
    const int r0 = rg * 4;
    const ull* wbase = ws + gg * 6;
    const float* xbase = xs + r0 * KP_;

    ull acc[4][6];
    #pragma unroll
    for (int p = 0; p < 6; p++) {
        ull bb = bs[gg * 6 + p];
        acc[0][p] = bb; acc[1][p] = bb; acc[2][p] = bb; acc[3][p] = bb;
    }

    #pragma unroll
    for (int kc = 0; kc < KP_ / 4; kc++) {
        float4 xq[4];
        #pragma unroll
        for (int i = 0; i < 4; i++)
            xq[i] = *reinterpret_cast<const float4*>(xbase + i * KP_ + kc * 4);

        #pragma unroll
        for (int kk = 0; kk < 4; kk++) {
            ull X[4];
            #pragma unroll
            for (int i = 0; i < 4; i++) {
                float xv = (kk == 0) ? xq[i].x : (kk == 1) ? xq[i].y
                         : (kk == 2) ? xq[i].z : xq[i].w;
                X[i] = pk2(xv, xv);
            }
            const ulonglong2* wk =
                reinterpret_cast<const ulonglong2*>(wbase + (kc * 4 + kk) * 36);
            ulonglong2 wA = wk[0], wB = wk[1], wC = wk[2];
            #pragma unroll
            for (int i = 0; i < 4; i++) {
                acc[i][0] = ffma2(X[i], wA.x, acc[i][0]);
                acc[i][1] = ffma2(X[i], wA.y, acc[i][1]);
                acc[i][2] = ffma2(X[i], wB.x, acc[i][2]);
                acc[i][3] = ffma2(X[i], wB.y, acc[i][3]);
                acc[i][4] = ffma2(X[i], wC.x, acc[i][4]);
                acc[i][5] = ffma2(X[i], wC.y, acc[i][5]);
            }
        }
    }

    __syncthreads();
    ull* os = reinterpret_cast<ull*>(sraw);
    #pragma unroll
    for (int i = 0; i < 4; i++) {
        #pragma unroll
        for (int p = 0; p < 6; p++) {
            os[(r0 + i) * 36 + gg * 6 + p] = acc[i][p];
        }
    }
    __syncthreads();
    {
        const float4* src = reinterpret_cast<const float4*>(sraw);
        float4* dst = reinterpret_cast<float4*>(g_xproj + rowbase * GP_);
        #pragma unroll
        for (int it = 0; it < 12; it++) {
            int idx = tid + it * 192;
            dst[idx] = src[idx];
        }
    }
}

// ============================================================================
// Kernel 2: GRU scan, GATE-SPLIT. Block = 96 threads = 3 warps = ONE batch row.
//   warp 0 -> r gate, warp 1 -> z gate, warp 2 -> n gate + h update.
//   Each warp: 12 FFMA2 matvec for its gate. 2 __syncthreads per step.
//   10.4 warps/SMSP (vs 3.46 before) -> issue-bound instead of latency-bound.
//   h double-buffered in smem; b_hh folded via pad slot h[23]==1.
//   x ring-prefetch depth 4, copy-free (LDG lands in consumed register).
// ============================================================================
__global__ __launch_bounds__(96) void gru_scan_kernel(
    const float* __restrict__ Whh,    // [69][23]
    const float* __restrict__ bhh,    // [69]
    const float* __restrict__ piw,    // [23]
    const float* __restrict__ pib,    // [23]
    float* __restrict__ out_action,   // [B][T][23]
    float* __restrict__ out_hidden)   // [B][23]
{
    __shared__ __align__(16) float hsm[2][32];   // double-buffered h (+pad=1)
    __shared__ float rsm[32];
    __shared__ float zsm[32];

    const int j  = threadIdx.x & 31;
    const int w  = threadIdx.x >> 5;     // 0=r, 1=z, 2=n
    const int b  = blockIdx.x;
    const int jc = (j < H_) ? j : (H_ - 1);
    const bool act = (j < H_);

    // This warp's gate row of W_hh for unit jc: 12 k-pairs, pad carries b_hh
    ull W[12];
    {
        const int grow = w * H_ + jc;
        const float* wp_ = Whh + (size_t)grow * H_;
        #pragma unroll
        for (int m = 0; m < 11; m++)
            W[m] = pk2(wp_[2 * m], wp_[2 * m + 1]);
        W[11] = pk2(wp_[22], bhh[grow]);
    }
    const float pw = piw[jc], pb = pib[jc];

    // init h buffers: zeros + pad slot 23 = 1.0 (bias carrier); 24..31 unused
    if (w == 0) {
        float v = (j == 23) ? 1.0f : 0.0f;
        hsm[0][j] = v;
        hsm[1][j] = v;
    }
    __syncthreads();

    const float* xp = g_xproj + (size_t)b * T_ * GP_ + w * H_ + jc;
    float* outp = out_action + (size_t)b * T_ * H_;

    // ring prefetch: X[s] holds this gate's x for step t = group+s
    float X[4];
    #pragma unroll
    for (int s = 0; s < 4; s++) X[s] = xp[s * GP_];

    float h = 0.0f;   // only meaningful in warp 2 (n/update warp)

    #pragma unroll 1
    for (int tb = 0; tb < T_; tb += 4) {
        #pragma unroll
        for (int s = 0; s < 4; s++) {
            const int t = tb + s;
            // --- matvec for own gate against h(t) ---
            const ulonglong2* hq =
                reinterpret_cast<const ulonglong2*>(hsm[t & 1]);
            ull a = 0ull;
            #pragma unroll
            for (int m = 0; m < 6; m++) {
                ulonglong2 q = hq[m];
                a = ffma2(W[2 * m], q.x, a);
                a = ffma2(W[2 * m + 1], q.y, a);
            }
            float lo, hi;
            upk2(a, lo, hi);
            float hg = lo + hi;          // includes b_hh via pad slot

            if (w == 0) {
                if (act) rsm[j] = fsigmoid(X[s] + hg);
            } else if (w == 1) {
                if (act) zsm[j] = fsigmoid(X[s] + hg);
            }
            __syncthreads();             // r,z published

            if (w == 2) {
                float r = rsm[j];
                float z = zsm[j];
                float n = ftanh(fmaf(r, hg, X[s]));   // hg here is hn
                float hnew = fmaf(z, h - n, n);       // (1-z)*n + z*h
                if (act) {
                    hsm[(t + 1) & 1][j] = hnew;
                    outp[(size_t)t * H_ + j] = fmaf(pw, hnew, pb);
                }
                h = hnew;
            }
            __syncthreads();             // h(t+1) published

            // refill ring slot for t+4 (consumed next group; copy-free)
            int tn = (t + 4 < T_) ? t + 4 : T_ - 1;
            X[s] = xp[(size_t)tn * GP_];
        }
    }

    if (w == 2 && act) out_hidden[(size_t)b * H_ + j] = h;
}

// ============================================================================
extern "C" void kernel_launch(void* const* d_in, const int* in_sizes, int n_in,
                              void* d_out, int out_size) {
    const float* task = (const float*)d_in[0];  // (2048,512,58)
    const float* Wih  = (const float*)d_in[1];  // (69,58)
    const float* Whh  = (const float*)d_in[2];  // (69,23)
    const float* bih  = (const float*)d_in[3];  // (69)
    const float* bhh  = (const float*)d_in[4];  // (69)
    const float* piw  = (const float*)d_in[5];  // (23)
    const float* pib  = (const float*)d_in[6];  // (23)

    float* out = (float*)d_out;
    float* action = out;                                  // B*T*H
    float* hidden = out + (size_t)B_ * T_ * H_;           // B*H

    gemm_xproj_kernel<<<ROWS_ / 128, 192>>>(task, Wih, bih);
    gru_scan_kernel<<<B_, 96>>>(Whh, bhh, piw, pib, action, hidden);
}

// round 6
// speedup vs baseline: 1.3845x; 1.1796x over previous
#include <cuda_runtime.h>
#include <cstdint>

typedef unsigned long long ull;

// Problem constants
#define B_  2048
#define T_  512
#define I_  58
#define KP_ 60          // padded k (multiple of 4)
#define H_  23
#define G_  69          // 3*H
#define GP_ 72          // padded gate dim
#define ROWS_ (B_*T_)   // 1048576

// Scratch for x_proj: [B*T][72] padded
__device__ float g_xproj[(size_t)ROWS_ * GP_];

// ---------------- f32x2 helpers ----------------
__device__ __forceinline__ ull pk2(float a, float b) {
    ull r;
    asm("mov.b64 %0, {%1, %2};" : "=l"(r) : "f"(a), "f"(b));
    return r;
}
__device__ __forceinline__ void upk2(ull v, float& a, float& b) {
    asm("mov.b64 {%0, %1}, %2;" : "=f"(a), "=f"(b) : "l"(v));
}
__device__ __forceinline__ ull ffma2(ull a, ull b, ull c) {
    ull d;
    asm("fma.rn.f32x2 %0, %1, %2, %3;" : "=l"(d) : "l"(a), "l"(b), "l"(c));
    return d;
}
__device__ __forceinline__ ull add2(ull a, ull b) {
    ull d;
    asm("add.rn.f32x2 %0, %1, %2;" : "=l"(d) : "l"(a), "l"(b));
    return d;
}
// ---------------- fast transcendentals ----------------
__device__ __forceinline__ float fex2(float x) {
    float y; asm("ex2.approx.f32 %0, %1;" : "=f"(y) : "f"(x)); return y;
}
__device__ __forceinline__ float frcp(float x) {
    float y; asm("rcp.approx.f32 %0, %1;" : "=f"(y) : "f"(x)); return y;
}
__device__ __forceinline__ float fsigmoid(float x) {
    return frcp(1.0f + fex2(-1.4426950408889634f * x));
}
__device__ __forceinline__ float ftanh(float x) {
    float e = fex2(2.8853900817779268f * x);
    return fmaf(-2.0f, frcp(e + 1.0f), 1.0f);
}

// ============================================================================
// Kernel 1: x_proj = task @ W_ih^T + b_ih
//   64 rows/block, 192 threads. Thread: 2 rows x 6 g-pairs (24 acc regs).
//   Small per-thread tile -> ~60 regs, NO SPILLS, 5 blocks/SM.
// ============================================================================
__global__ __launch_bounds__(192, 5) void gemm_xproj_kernel(
    const float* __restrict__ task,   // [B*T][58]
    const float* __restrict__ Wih,    // [69][58]
    const float* __restrict__ bih)    // [69]
{
    // xs: [64][60] floats (15360B) ; ws: [60][36] ull g-pairs (17280B)
    // restage reuse needs 64*36*8 = 18432B <= 32640B total
    __shared__ __align__(16) char sraw[64 * KP_ * 4 + KP_ * 36 * 8];
    float* xs = reinterpret_cast<float*>(sraw);
    ull*   ws = reinterpret_cast<ull*>(sraw + 64 * KP_ * 4);
    __shared__ __align__(16) ull bs[36];

    const int tid = threadIdx.x;
    const size_t rowbase = (size_t)blockIdx.x * 64;

    // Stage x tile: coalesced float4 loads (64*58/4 = 928), scatter to 60-pad
    {
        const float4* src = reinterpret_cast<const float4*>(task + rowbase * I_);
        #pragma unroll
        for (int it = 0; it < 5; it++) {
            int v = tid + it * 192;
            if (v < (64 * I_ / 4)) {
                float4 f = src[v];
                int e = 4 * v;
                int r = e / I_, c = e - r * I_;
                float vals[4] = {f.x, f.y, f.z, f.w};
                #pragma unroll
                for (int q = 0; q < 4; q++) {
                    int rr = r, cc = c + q;
                    if (cc >= I_) { rr += 1; cc -= I_; }
                    xs[rr * KP_ + cc] = vals[q];
                }
            }
        }
        // zero pad cols 58,59 (64 rows x 2)
        if (tid < 128) {
            int r = tid >> 1, c = I_ + (tid & 1);
            xs[r * KP_ + c] = 0.0f;
        }
    }
    // Stage weights as (k, g-pair); zero beyond k=57 / g=68
    for (int i = tid; i < KP_ * 36; i += 192) {
        int k = i / 36, p = i - 36 * k;
        int g0 = 2 * p;
        float w0 = (k < I_ && g0     < G_) ? Wih[g0 * I_ + k]       : 0.0f;
        float w1 = (k < I_ && g0 + 1 < G_) ? Wih[(g0 + 1) * I_ + k] : 0.0f;
        float2 wp = make_float2(w0, w1);
        ws[i] = *reinterpret_cast<ull*>(&wp);
    }
    if (tid < 36) {
        int g0 = 2 * tid;
        float b0 = (g0     < G_) ? bih[g0]     : 0.0f;
        float b1 = (g0 + 1 < G_) ? bih[g0 + 1] : 0.0f;
        float2 bp = make_float2(b0, b1);
        bs[tid] = *reinterpret_cast<ull*>(&bp);
    }
    __syncthreads();

    const int gg = tid % 6;      // 6 pair-tiles of 6 pairs = 36 pairs = 72 g
    const int rg = tid / 6;      // 32 row groups of 2 rows
    const int r0 = rg * 2;
    const ull* wbase = ws + gg * 6;
    const float* xbase = xs + r0 * KP_;

    ull acc[2][6];
    #pragma unroll
    for (int p = 0; p < 6; p++) {
        ull bb = bs[gg * 6 + p];
        acc[0][p] = bb; acc[1][p] = bb;
    }

    #pragma unroll
    for (int kc = 0; kc < KP_ / 4; kc++) {
        float4 xq0 = *reinterpret_cast<const float4*>(xbase + kc * 4);
        float4 xq1 = *reinterpret_cast<const float4*>(xbase + KP_ + kc * 4);

        #pragma unroll
        for (int kk = 0; kk < 4; kk++) {
            float x0 = (kk == 0) ? xq0.x : (kk == 1) ? xq0.y
                     : (kk == 2) ? xq0.z : xq0.w;
            float x1 = (kk == 0) ? xq1.x : (kk == 1) ? xq1.y
                     : (kk == 2) ? xq1.z : xq1.w;
            ull X0 = pk2(x0, x0);
            ull X1 = pk2(x1, x1);
            const ulonglong2* wk =
                reinterpret_cast<const ulonglong2*>(wbase + (kc * 4 + kk) * 36);
            ulonglong2 wA = wk[0], wB = wk[1], wC = wk[2];
            acc[0][0] = ffma2(X0, wA.x, acc[0][0]);
            acc[0][1] = ffma2(X0, wA.y, acc[0][1]);
            acc[0][2] = ffma2(X0, wB.x, acc[0][2]);
            acc[0][3] = ffma2(X0, wB.y, acc[0][3]);
            acc[0][4] = ffma2(X0, wC.x, acc[0][4]);
            acc[0][5] = ffma2(X0, wC.y, acc[0][5]);
            acc[1][0] = ffma2(X1, wA.x, acc[1][0]);
            acc[1][1] = ffma2(X1, wA.y, acc[1][1]);
            acc[1][2] = ffma2(X1, wB.x, acc[1][2]);
            acc[1][3] = ffma2(X1, wB.y, acc[1][3]);
            acc[1][4] = ffma2(X1, wC.x, acc[1][4]);
            acc[1][5] = ffma2(X1, wC.y, acc[1][5]);
        }
    }

    __syncthreads();   // xs/ws dead; reuse as output stage
    ull* os = reinterpret_cast<ull*>(sraw);   // [64][36] pairs
    #pragma unroll
    for (int i = 0; i < 2; i++) {
        #pragma unroll
        for (int p = 0; p < 6; p++) {
            os[(r0 + i) * 36 + gg * 6 + p] = acc[i][p];
        }
    }
    __syncthreads();
    // Coalesced float4 streamout: 64*72/4 = 1152 vectors, 6 per thread
    {
        const float4* src = reinterpret_cast<const float4*>(sraw);
        float4* dst = reinterpret_cast<float4*>(g_xproj + rowbase * GP_);
        #pragma unroll
        for (int it = 0; it < 6; it++) {
            int idx = tid + it * 192;
            dst[idx] = src[idx];
        }
    }
}

// ============================================================================
// Kernel 2: GRU scan (R3 skeleton). 4 warps/block, one batch row per warp.
//   Change vs R3: TWO parallel accumulator chains per gate (halves the
//   12-deep FFMA2 serial chain), combined with add.rn.f32x2.
// ============================================================================
__global__ __launch_bounds__(128, 4) void gru_scan_kernel(
    const float* __restrict__ Whh,    // [69][23]
    const float* __restrict__ bhh,    // [69]
    const float* __restrict__ piw,    // [23]
    const float* __restrict__ pib,    // [23]
    float* __restrict__ out_action,   // [B][T][23]
    float* __restrict__ out_hidden)   // [B][23]
{
    __shared__ __align__(16) float hsm[4][2][32];

    const int j  = threadIdx.x & 31;
    const int w  = threadIdx.x >> 5;
    const int b  = blockIdx.x * 4 + w;
    const int jc = (j < H_) ? j : (H_ - 1);
    const bool act = (j < H_);

    // W_hh rows for unit jc, 12 k-pairs; pad slot carries b_hh (h[23]==1)
    ull WR[12], WZ[12], WN[12];
    {
        const float* wr = Whh + (size_t)jc * H_;
        const float* wz = Whh + (size_t)(H_ + jc) * H_;
        const float* wn = Whh + (size_t)(2 * H_ + jc) * H_;
        #pragma unroll
        for (int m = 0; m < 11; m++) {
            WR[m] = pk2(wr[2 * m], wr[2 * m + 1]);
            WZ[m] = pk2(wz[2 * m], wz[2 * m + 1]);
            WN[m] = pk2(wn[2 * m], wn[2 * m + 1]);
        }
        WR[11] = pk2(wr[22], bhh[jc]);
        WZ[11] = pk2(wz[22], bhh[H_ + jc]);
        WN[11] = pk2(wn[22], bhh[2 * H_ + jc]);
    }
    const float pw = piw[jc], pb = pib[jc];

    // init both h buffers: zeros + pad slot [23] = 1.0 (bias carrier)
    hsm[w][0][j] = (j == 23) ? 1.0f : 0.0f;
    hsm[w][1][j] = (j == 23) ? 1.0f : 0.0f;
    __syncwarp();

    const float* xp = g_xproj + (size_t)b * T_ * GP_;
    float* outp = out_action + (size_t)b * T_ * H_;
    const int o0 = jc, o1 = H_ + jc, o2 = 2 * H_ + jc;

    // prime pipeline with group t=0..3
    float cur[12];
    #pragma unroll
    for (int s = 0; s < 4; s++) {
        const float* xr = xp + s * GP_;
        cur[3 * s + 0] = xr[o0];
        cur[3 * s + 1] = xr[o1];
        cur[3 * s + 2] = xr[o2];
    }

    float h = 0.0f;

    #pragma unroll 2
    for (int tb = 0; tb < T_; tb += 4) {
        const float* xn_ = xp + (size_t)((tb + 4 < T_) ? tb + 4 : T_ - 4) * GP_;
        #pragma unroll
        for (int s = 0; s < 4; s++) {
            // ---- matvec: two parallel chains per gate ----
            const ulonglong2* hq =
                reinterpret_cast<const ulonglong2*>(hsm[w][s & 1]);
            ull aR0 = 0, aR1 = 0, aZ0 = 0, aZ1 = 0, aN0 = 0, aN1 = 0;
            #pragma unroll
            for (int m = 0; m < 6; m++) {
                ulonglong2 q = hq[m];
                aR0 = ffma2(WR[2 * m],     q.x, aR0);
                aR1 = ffma2(WR[2 * m + 1], q.y, aR1);
                aZ0 = ffma2(WZ[2 * m],     q.x, aZ0);
                aZ1 = ffma2(WZ[2 * m + 1], q.y, aZ1);
                aN0 = ffma2(WN[2 * m],     q.x, aN0);
                aN1 = ffma2(WN[2 * m + 1], q.y, aN1);
            }
            ull aR = add2(aR0, aR1);
            ull aZ = add2(aZ0, aZ1);
            ull aN = add2(aN0, aN1);
            float rl, rh, zl, zh, nl, nh;
            upk2(aR, rl, rh); upk2(aZ, zl, zh); upk2(aN, nl, nh);

            float r = fsigmoid(cur[3 * s + 0] + (rl + rh));
            float z = fsigmoid(cur[3 * s + 1] + (zl + zh));
            float n = ftanh(fmaf(r, nl + nh, cur[3 * s + 2]));
            float hnew = fmaf(z, h - n, n);        // (1-z)*n + z*h

            if (act) hsm[w][(s + 1) & 1][j] = hnew;
            __syncwarp();

            if (act) outp[(size_t)(tb + s) * H_ + j] = fmaf(pw, hnew, pb);
            h = hnew;

            // refill slot for t+4 (deep prefetch)
            cur[3 * s + 0] = xn_[s * GP_ + o0];
            cur[3 * s + 1] = xn_[s * GP_ + o1];
            cur[3 * s + 2] = xn_[s * GP_ + o2];
        }
    }

    if (act) out_hidden[(size_t)b * H_ + j] = h;
}

// ============================================================================
extern "C" void kernel_launch(void* const* d_in, const int* in_sizes, int n_in,
                              void* d_out, int out_size) {
    const float* task = (const float*)d_in[0];  // (2048,512,58)
    const float* Wih  = (const float*)d_in[1];  // (69,58)
    const float* Whh  = (const float*)d_in[2];  // (69,23)
    const float* bih  = (const float*)d_in[3];  // (69)
    const float* bhh  = (const float*)d_in[4];  // (69)
    const float* piw  = (const float*)d_in[5];  // (23)
    const float* pib  = (const float*)d_in[6];  // (23)

    float* out = (float*)d_out;
    float* action = out;                                  // B*T*H
    float* hidden = out + (size_t)B_ * T_ * H_;           // B*H

    gemm_xproj_kernel<<<ROWS_ / 64, 192>>>(task, Wih, bih);
    gru_scan_kernel<<<B_ / 4, 128>>>(Whh, bhh, piw, pib, action, hidden);
}

// round 7
// speedup vs baseline: 1.6627x; 1.2010x over previous
#include <cuda_runtime.h>
#include <cstdint>

typedef unsigned long long ull;

// Problem constants
#define B_  2048
#define T_  512
#define I_  58
#define KP_ 60          // padded k (multiple of 4)
#define H_  23
#define G_  69          // 3*H
#define GP_ 72          // padded gate dim
#define ROWS_ (B_*T_)   // 1048576

// Scratch for x_proj: [B*T][72] padded
__device__ float g_xproj[(size_t)ROWS_ * GP_];

// ---------------- f32x2 helpers ----------------
__device__ __forceinline__ ull pk2(float a, float b) {
    ull r;
    asm("mov.b64 %0, {%1, %2};" : "=l"(r) : "f"(a), "f"(b));
    return r;
}
__device__ __forceinline__ void upk2(ull v, float& a, float& b) {
    asm("mov.b64 {%0, %1}, %2;" : "=f"(a), "=f"(b) : "l"(v));
}
__device__ __forceinline__ ull ffma2(ull a, ull b, ull c) {
    ull d;
    asm("fma.rn.f32x2 %0, %1, %2, %3;" : "=l"(d) : "l"(a), "l"(b), "l"(c));
    return d;
}
__device__ __forceinline__ ull add2(ull a, ull b) {
    ull d;
    asm("add.rn.f32x2 %0, %1, %2;" : "=l"(d) : "l"(a), "l"(b));
    return d;
}
// ---------------- fast transcendentals ----------------
__device__ __forceinline__ float fex2(float x) {
    float y; asm("ex2.approx.f32 %0, %1;" : "=f"(y) : "f"(x)); return y;
}
__device__ __forceinline__ float frcp(float x) {
    float y; asm("rcp.approx.f32 %0, %1;" : "=f"(y) : "f"(x)); return y;
}
__device__ __forceinline__ float fsigmoid(float x) {
    return frcp(1.0f + fex2(-1.4426950408889634f * x));
}
__device__ __forceinline__ float ftanh(float x) {
    float e = fex2(2.8853900817779268f * x);
    return fmaf(-2.0f, frcp(e + 1.0f), 1.0f);
}

// ============================================================================
// Kernel 1: x_proj = task @ W_ih^T + b_ih
//   128 rows/block (best staging amortization), 192 threads.
//   Thread: 4 rows x 6 g-pairs. KP=60-padded x -> LDS.128 k-quads.
//   __launch_bounds__(192,3): 113-reg cap -> NO SPILLS (live set ~90).
// ============================================================================
__global__ __launch_bounds__(192, 3) void gemm_xproj_kernel(
    const float* __restrict__ task,   // [B*T][58]
    const float* __restrict__ Wih,    // [69][58]
    const float* __restrict__ bih)    // [69]
{
    // xs: [128][60] floats (30720B) ; ws: [60][36] ull g-pairs (17280B)
    // restage reuse: os[128][36] ull = 36864B <= 48000B region
    __shared__ __align__(16) char sraw[128 * KP_ * 4 + KP_ * 36 * 8];
    float* xs = reinterpret_cast<float*>(sraw);
    ull*   ws = reinterpret_cast<ull*>(sraw + 128 * KP_ * 4);
    __shared__ __align__(16) ull bs[36];

    const int tid = threadIdx.x;
    const size_t rowbase = (size_t)blockIdx.x * 128;

    // Stage x tile: coalesced float4 loads (1856 vectors), scatter to 60-pad
    {
        const float4* src = reinterpret_cast<const float4*>(task + rowbase * I_);
        #pragma unroll
        for (int it = 0; it < 10; it++) {
            int v = tid + it * 192;
            if (it < 9 || tid < 128) {
                float4 f = src[v];
                int e = 4 * v;
                int r = e / I_, c = e - r * I_;
                float vals[4] = {f.x, f.y, f.z, f.w};
                #pragma unroll
                for (int q = 0; q < 4; q++) {
                    int rr = r, cc = c + q;
                    if (cc >= I_) { rr += 1; cc -= I_; }
                    xs[rr * KP_ + cc] = vals[q];
                }
            }
        }
        // zero pad cols 58,59 (128 rows x 2 = 256 slots)
        for (int i = tid; i < 256; i += 192) {
            int r = i >> 1, c = I_ + (i & 1);
            xs[r * KP_ + c] = 0.0f;
        }
    }
    // Stage weights as (k, g-pair); zero beyond k=57 / g=68
    for (int i = tid; i < KP_ * 36; i += 192) {
        int k = i / 36, p = i - 36 * k;
        int g0 = 2 * p;
        float w0 = (k < I_ && g0     < G_) ? Wih[g0 * I_ + k]       : 0.0f;
        float w1 = (k < I_ && g0 + 1 < G_) ? Wih[(g0 + 1) * I_ + k] : 0.0f;
        float2 wp = make_float2(w0, w1);
        ws[i] = *reinterpret_cast<ull*>(&wp);
    }
    if (tid < 36) {
        int g0 = 2 * tid;
        float b0 = (g0     < G_) ? bih[g0]     : 0.0f;
        float b1 = (g0 + 1 < G_) ? bih[g0 + 1] : 0.0f;
        float2 bp = make_float2(b0, b1);
        bs[tid] = *reinterpret_cast<ull*>(&bp);
    }
    __syncthreads();

    const int gg = tid % 6;      // 6 pair-tiles of 6 pairs = 36 pairs = 72 g
    const int rg = tid / 6;      // 32 row groups of 4 rows
    const int r0 = rg * 4;
    const ull* wbase = ws + gg * 6;
    const float* xbase = xs + r0 * KP_;

    ull acc[4][6];
    #pragma unroll
    for (int p = 0; p < 6; p++) {
        ull bb = bs[gg * 6 + p];
        acc[0][p] = bb; acc[1][p] = bb; acc[2][p] = bb; acc[3][p] = bb;
    }

    #pragma unroll
    for (int kc = 0; kc < KP_ / 4; kc++) {
        // 4 rows x 4 k's via LDS.128 (60-float rows -> 16B aligned)
        float4 xq[4];
        #pragma unroll
        for (int i = 0; i < 4; i++)
            xq[i] = *reinterpret_cast<const float4*>(xbase + i * KP_ + kc * 4);

        #pragma unroll
        for (int kk = 0; kk < 4; kk++) {
            ull X[4];
            #pragma unroll
            for (int i = 0; i < 4; i++) {
                float xv = (kk == 0) ? xq[i].x : (kk == 1) ? xq[i].y
                         : (kk == 2) ? xq[i].z : xq[i].w;
                X[i] = pk2(xv, xv);
            }
            const ulonglong2* wk =
                reinterpret_cast<const ulonglong2*>(wbase + (kc * 4 + kk) * 36);
            ulonglong2 wA = wk[0], wB = wk[1], wC = wk[2];
            #pragma unroll
            for (int i = 0; i < 4; i++) {
                acc[i][0] = ffma2(X[i], wA.x, acc[i][0]);
                acc[i][1] = ffma2(X[i], wA.y, acc[i][1]);
                acc[i][2] = ffma2(X[i], wB.x, acc[i][2]);
                acc[i][3] = ffma2(X[i], wB.y, acc[i][3]);
                acc[i][4] = ffma2(X[i], wC.x, acc[i][4]);
                acc[i][5] = ffma2(X[i], wC.y, acc[i][5]);
            }
        }
    }

    __syncthreads();   // xs/ws dead; reuse as output stage
    ull* os = reinterpret_cast<ull*>(sraw);   // [128][36] pairs
    #pragma unroll
    for (int i = 0; i < 4; i++) {
        #pragma unroll
        for (int p = 0; p < 6; p++) {
            os[(r0 + i) * 36 + gg * 6 + p] = acc[i][p];
        }
    }
    __syncthreads();
    // Coalesced float4 streamout: 128*72/4 = 2304 vectors, 12 per thread
    {
        const float4* src = reinterpret_cast<const float4*>(sraw);
        float4* dst = reinterpret_cast<float4*>(g_xproj + rowbase * GP_);
        #pragma unroll
        for (int it = 0; it < 12; it++) {
            int idx = tid + it * 192;
            dst[idx] = src[idx];
        }
    }
}

// ============================================================================
// Kernel 2: GRU scan (unchanged R6 — best measured). 4 warps/block,
//   one batch row per warp, weights in registers, 1 syncwarp/step,
//   two parallel accumulator chains per gate, 4-step x prefetch.
// ============================================================================
__global__ __launch_bounds__(128, 4) void gru_scan_kernel(
    const float* __restrict__ Whh,    // [69][23]
    const float* __restrict__ bhh,    // [69]
    const float* __restrict__ piw,    // [23]
    const float* __restrict__ pib,    // [23]
    float* __restrict__ out_action,   // [B][T][23]
    float* __restrict__ out_hidden)   // [B][23]
{
    __shared__ __align__(16) float hsm[4][2][32];

    const int j  = threadIdx.x & 31;
    const int w  = threadIdx.x >> 5;
    const int b  = blockIdx.x * 4 + w;
    const int jc = (j < H_) ? j : (H_ - 1);
    const bool act = (j < H_);

    // W_hh rows for unit jc, 12 k-pairs; pad slot carries b_hh (h[23]==1)
    ull WR[12], WZ[12], WN[12];
    {
        const float* wr = Whh + (size_t)jc * H_;
        const float* wz = Whh + (size_t)(H_ + jc) * H_;
        const float* wn = Whh + (size_t)(2 * H_ + jc) * H_;
        #pragma unroll
        for (int m = 0; m < 11; m++) {
            WR[m] = pk2(wr[2 * m], wr[2 * m + 1]);
            WZ[m] = pk2(wz[2 * m], wz[2 * m + 1]);
            WN[m] = pk2(wn[2 * m], wn[2 * m + 1]);
        }
        WR[11] = pk2(wr[22], bhh[jc]);
        WZ[11] = pk2(wz[22], bhh[H_ + jc]);
        WN[11] = pk2(wn[22], bhh[2 * H_ + jc]);
    }
    const float pw = piw[jc], pb = pib[jc];

    // init both h buffers: zeros + pad slot [23] = 1.0 (bias carrier)
    hsm[w][0][j] = (j == 23) ? 1.0f : 0.0f;
    hsm[w][1][j] = (j == 23) ? 1.0f : 0.0f;
    __syncwarp();

    const float* xp = g_xproj + (size_t)b * T_ * GP_;
    float* outp = out_action + (size_t)b * T_ * H_;
    const int o0 = jc, o1 = H_ + jc, o2 = 2 * H_ + jc;

    // prime pipeline with group t=0..3
    float cur[12];
    #pragma unroll
    for (int s = 0; s < 4; s++) {
        const float* xr = xp + s * GP_;
        cur[3 * s + 0] = xr[o0];
        cur[3 * s + 1] = xr[o1];
        cur[3 * s + 2] = xr[o2];
    }

    float h = 0.0f;

    #pragma unroll 2
    for (int tb = 0; tb < T_; tb += 4) {
        const float* xn_ = xp + (size_t)((tb + 4 < T_) ? tb + 4 : T_ - 4) * GP_;
        #pragma unroll
        for (int s = 0; s < 4; s++) {
            // ---- matvec: two parallel chains per gate ----
            const ulonglong2* hq =
                reinterpret_cast<const ulonglong2*>(hsm[w][s & 1]);
            ull aR0 = 0, aR1 = 0, aZ0 = 0, aZ1 = 0, aN0 = 0, aN1 = 0;
            #pragma unroll
            for (int m = 0; m < 6; m++) {
                ulonglong2 q = hq[m];
                aR0 = ffma2(WR[2 * m],     q.x, aR0);
                aR1 = ffma2(WR[2 * m + 1], q.y, aR1);
                aZ0 = ffma2(WZ[2 * m],     q.x, aZ0);
                aZ1 = ffma2(WZ[2 * m + 1], q.y, aZ1);
                aN0 = ffma2(WN[2 * m],     q.x, aN0);
                aN1 = ffma2(WN[2 * m + 1], q.y, aN1);
            }
            ull aR = add2(aR0, aR1);
            ull aZ = add2(aZ0, aZ1);
            ull aN = add2(aN0, aN1);
            float rl, rh, zl, zh, nl, nh;
            upk2(aR, rl, rh); upk2(aZ, zl, zh); upk2(aN, nl, nh);

            float r = fsigmoid(cur[3 * s + 0] + (rl + rh));
            float z = fsigmoid(cur[3 * s + 1] + (zl + zh));
            float n = ftanh(fmaf(r, nl + nh, cur[3 * s + 2]));
            float hnew = fmaf(z, h - n, n);        // (1-z)*n + z*h

            if (act) hsm[w][(s + 1) & 1][j] = hnew;
            __syncwarp();

            if (act) outp[(size_t)(tb + s) * H_ + j] = fmaf(pw, hnew, pb);
            h = hnew;

            // refill slot for t+4 (deep prefetch)
            cur[3 * s + 0] = xn_[s * GP_ + o0];
            cur[3 * s + 1] = xn_[s * GP_ + o1];
            cur[3 * s + 2] = xn_[s * GP_ + o2];
        }
    }

    if (act) out_hidden[(size_t)b * H_ + j] = h;
}

// ============================================================================
extern "C" void kernel_launch(void* const* d_in, const int* in_sizes, int n_in,
                              void* d_out, int out_size) {
    const float* task = (const float*)d_in[0];  // (2048,512,58)
    const float* Wih  = (const float*)d_in[1];  // (69,58)
    const float* Whh  = (const float*)d_in[2];  // (69,23)
    const float* bih  = (const float*)d_in[3];  // (69)
    const float* bhh  = (const float*)d_in[4];  // (69)
    const float* piw  = (const float*)d_in[5];  // (23)
    const float* pib  = (const float*)d_in[6];  // (23)

    float* out = (float*)d_out;
    float* action = out;                                  // B*T*H
    float* hidden = out + (size_t)B_ * T_ * H_;           // B*H

    gemm_xproj_kernel<<<ROWS_ / 128, 192>>>(task, Wih, bih);
    gru_scan_kernel<<<B_ / 4, 128>>>(Whh, bhh, piw, pib, action, hidden);
}